// round 1
// baseline (speedup 1.0000x reference)
#include <cuda_runtime.h>
#include <stdint.h>

// Problem constants (fixed by the reference):
//   B=256 graphs, M=512 atoms each, K=33 neighbors (incl. self), radius 5.0
//   Output (float32, concatenated): src[E], dst[E], dist[E], mask[E], E = B*M*K
#define BGRAPH   256
#define MPTS     512
#define KNN      33
#define NTHREADS 512
#define RADIUS   5.0f

typedef unsigned long long ull;

// Shared layout: heap [KNN][MPTS] ull (transposed: conflict-free per-lane columns),
// then tile [MPTS] float4 (x,y,z,|p|^2).
#define HEAP_BYTES (KNN * MPTS * sizeof(ull))
#define TILE_BYTES (MPTS * sizeof(float4))
#define SMEM_BYTES (HEAP_BYTES + TILE_BYTES)

// Max-heap sift-down on the transposed shared heap. h[k*MPTS + q] is slot k of query q.
__device__ __forceinline__ void sift_down(ull* __restrict__ h, int q, int start, int n, ull val) {
    int p = start;
    for (;;) {
        int l = 2 * p + 1;
        if (l >= n) break;
        ull c = h[l * MPTS + q];
        int ci = l;
        int r = l + 1;
        if (r < n) {
            ull cr = h[r * MPTS + q];
            if (cr > c) { c = cr; ci = r; }
        }
        if (c <= val) break;
        h[p * MPTS + q] = c;
        p = ci;
    }
    h[p * MPTS + q] = val;
}

extern "C" __global__ void __launch_bounds__(NTHREADS, 1)
knn_graph_kernel(const float* __restrict__ pos, float* __restrict__ out)
{
    extern __shared__ unsigned char smem[];
    ull*    h    = (ull*)smem;                       // [KNN][MPTS]
    float4* tile = (float4*)(smem + HEAP_BYTES);     // [MPTS]

    const int g    = blockIdx.x;
    const int tid  = threadIdx.x;
    const int base = g * MPTS;

    // ---- Stage positions: coalesced global->shared (scratch in heap area), then pack float4 ----
    {
        float* raw = (float*)h;  // reuse heap region as scratch (1536 floats)
        const float* gp = pos + (size_t)base * 3;
        for (int i = tid; i < MPTS * 3; i += NTHREADS) raw[i] = gp[i];
        __syncthreads();
        float x = raw[tid * 3 + 0];
        float y = raw[tid * 3 + 1];
        float z = raw[tid * 3 + 2];
        float s = x * x + y * y + z * z;   // same expression shape as dot() below -> self-d2 cancels to exactly 0
        tile[tid] = make_float4(x, y, z, s);
        __syncthreads();
    }

    const int q = tid;
    const float4 tq = tile[q];
    const float px = tq.x, py = tq.y, pz = tq.z, sq = tq.w;

    // ---- Fill first KNN candidates, then Floyd heapify (max-heap on (d2,idx) key) ----
    for (int c = 0; c < KNN; ++c) {
        float4 t = tile[c];
        float dot = px * t.x + py * t.y + pz * t.z;
        float d2  = fmaf(-2.0f, dot, sq + t.w);      // reference's ||x||^2+||y||^2-2xy expansion
        d2 = fmaxf(d2, 0.0f);
        ull key = ((ull)__float_as_uint(d2) << 32) | (unsigned)c;
        h[c * MPTS + q] = key;
    }
    for (int i = KNN / 2 - 1; i >= 0; --i) {
        ull v = h[i * MPTS + q];
        sift_down(h, q, i, KNN, v);
    }
    ull rootKey = h[q];   // h[0][q] = current 33rd-smallest (max of kept set)

    // ---- Scan remaining candidates ----
    #pragma unroll 4
    for (int c = KNN; c < MPTS; ++c) {
        float4 t = tile[c];
        float dot = px * t.x + py * t.y + pz * t.z;
        float d2  = fmaf(-2.0f, dot, sq + t.w);
        d2 = fmaxf(d2, 0.0f);
        ull key = ((ull)__float_as_uint(d2) << 32) | (unsigned)c;
        if (key < rootKey) {
            sift_down(h, q, 0, KNN, key);
            rootKey = h[q];
        }
    }

    // ---- Heapsort -> ascending (d2, idx): matches lax.top_k order incl. tie-break ----
    for (int end = KNN - 1; end > 0; --end) {
        ull maxv = h[q];
        ull last = h[end * MPTS + q];
        h[end * MPTS + q] = maxv;
        sift_down(h, q, 0, end, last);
    }
    __syncwarp();  // output phase reads other lanes' heap columns (intra-warp only)

    // ---- Coalesced output: warp covers its 32 queries' 32*33 edges linearly ----
    const int warp = tid >> 5;
    const int lane = tid & 31;
    const int q0   = warp << 5;
    const long E   = (long)BGRAPH * MPTS * KNN;      // 4,325,376
    const long eBase = (long)(base + q0) * KNN;

    for (int j = lane; j < 32 * KNN; j += 32) {
        int qi = j / KNN;
        int qq = q0 + qi;
        int k  = j - qi * KNN;
        ull key = h[k * MPTS + qq];
        int c = (int)(unsigned)(key & 0xffffffffu);

        float4 a = tile[c];    // src = neighbor
        float4 b = tile[qq];   // dst = center
        float dx = a.x - b.x, dy = a.y - b.y, dz = a.z - b.z;
        float dd = dx * dx + dy * dy + dz * dz;      // reference recomputes dist from gathered endpoints
        float dist = (dd > 0.0f) ? sqrtf(dd) : 0.0f;

        long e = eBase + j;
        out[e]         = (float)(base + c);               // edge_index[0] = src
        out[E + e]     = (float)(base + qq);              // edge_index[1] = dst
        out[2 * E + e] = dist;                            // dist
        out[3 * E + e] = (dist <= RADIUS) ? 1.0f : 0.0f;  // mask
    }
}

extern "C" void kernel_launch(void* const* d_in, const int* in_sizes, int n_in,
                              void* d_out, int out_size) {
    const float* pos = (const float*)d_in[0];   // [B*M, 3] float32 (d_in[1] = batch, unused: uniform)
    float* out = (float*)d_out;
    cudaFuncSetAttribute(knn_graph_kernel,
                         cudaFuncAttributeMaxDynamicSharedMemorySize, (int)SMEM_BYTES);
    knn_graph_kernel<<<BGRAPH, NTHREADS, SMEM_BYTES>>>(pos, out);
}

// round 5
// speedup vs baseline: 1.4137x; 1.4137x over previous
#include <cuda_runtime.h>
#include <stdint.h>

// B=256 graphs, M=512 atoms, K=33 neighbors (incl self), radius 5.0
// Output float32 concatenated: src[E], dst[E], dist[E], mask[E], E = B*M*K
#define BGRAPH 256
#define MPTS   512
#define KNN    33
#define QPB    256                       // queries per CTA (2 CTAs per graph)
#define NCTA   ((BGRAPH * MPTS) / QPB)   // 512
#define CAP    40                        // collect buffer capacity per query
#define RADIUS 5.0f

typedef unsigned long long ull;

// Shared layout (per CTA):
//   tile : float4[512]                      8192 B
//   bufD : u32 [CAP+1][QPB+1] (padded)     42148 B   (histogram overlaps this region;
//                                                     phases separated by __syncthreads)
//   bufI : u16 [CAP+1][QPB+2] (padded)     21156 B
// total 71496 B -> 3 CTAs/SM
#define BUFD_STRIDE (QPB + 1)            // words; +1 pad -> conflict-free column access
#define BUFI_STRIDE (QPB + 2)            // halves
#define TILE_BYTES  (MPTS * 16)
#define BUFD_BYTES  ((CAP + 1) * BUFD_STRIDE * 4)
#define BUFI_BYTES  ((CAP + 1) * BUFI_STRIDE * 2)
#define SMEM_BYTES  (TILE_BYTES + BUFD_BYTES + BUFI_BYTES)

// Composite 48-bit key: (d2_bits << 16) | idx  -> exact (d2, idx) lexicographic order,
// matching lax.top_k stability (ascending d2, lower index first on ties).
__device__ __forceinline__ ull ldk(const uint32_t* bD, const uint16_t* bI, int i) {
    return ((ull)bD[i * BUFD_STRIDE] << 16) | bI[i * BUFI_STRIDE];
}
__device__ __forceinline__ void stk(uint32_t* bD, uint16_t* bI, int i, ull k) {
    bD[i * BUFD_STRIDE] = (uint32_t)(k >> 16);
    bI[i * BUFI_STRIDE] = (uint16_t)k;
}

__device__ __forceinline__ void sift_down(uint32_t* bD, uint16_t* bI, int start, int nn, ull val) {
    int p = start;
    for (;;) {
        int l = 2 * p + 1;
        if (l >= nn) break;
        ull c = ldk(bD, bI, l);
        int ci = l;
        if (l + 1 < nn) {
            ull cr = ldk(bD, bI, l + 1);
            if (cr > c) { c = cr; ci = l + 1; }
        }
        if (c <= val) break;
        stk(bD, bI, p, c);
        p = ci;
    }
    stk(bD, bI, p, val);
}

extern "C" __global__ void __launch_bounds__(QPB, 3)
knn_graph_kernel(const float* __restrict__ pos, float* __restrict__ out)
{
    extern __shared__ unsigned char smem[];
    float4*   tile = (float4*)smem;
    uint32_t* bufD = (uint32_t*)(smem + TILE_BYTES);
    uint16_t* bufI = (uint16_t*)(smem + TILE_BYTES + BUFD_BYTES);
    uint32_t* hist = (uint32_t*)(smem + TILE_BYTES);   // overlaps bufD (dead after barrier below)

    const int cta  = blockIdx.x;
    const int g    = cta >> 1;
    const int qoff = (cta & 1) * QPB;
    const int base = g * MPTS;
    const int tid  = threadIdx.x;

    // ---- Stage positions: coalesced load, pack float4(x,y,z,|p|^2) ----
    {
        float* raw = (float*)(smem + TILE_BYTES);      // scratch in bufD region
        const float* gp = pos + (size_t)base * 3;
        for (int i = tid; i < MPTS * 3; i += QPB) raw[i] = gp[i];
        __syncthreads();
        for (int i = tid; i < MPTS; i += QPB) {
            float x = raw[i * 3 + 0], y = raw[i * 3 + 1], z = raw[i * 3 + 2];
            tile[i] = make_float4(x, y, z, x * x + y * y + z * z);
        }
        __syncthreads();
    }

    const int q = qoff + tid;                          // this thread's query (0..511 in graph)
    const float4 me = tile[q];
    const float px = me.x, py = me.y, pz = me.z, sq = me.w;

    // ---- Threshold refinement: per-thread private 32-bin histograms on d2 bits ----
    // hist[b][tid]: each thread owns disjoint words {b*256+tid} -> no cross-thread access.
    // Low-clamp bin keeps cumulative counts EXACT for b<31; high-clamp bin (31) inflates
    // nT, so we only trust (break on) bstar < 31. On bstar==31 we refine anyway: the 33rd
    // key provably lies inside bin 31's true range (>=33 keys below window end from the
    // previous pass; <33 below bin 31's lower edge), so refinement stays convergent.
    uint32_t* histq = hist + tid;
    uint32_t lo = 120u << 23;                          // octave bins: d2 in [2^-7, 2^24); bin31 unreachable pass 0
    int      sh = 23;
    uint32_t Tsel = 0xFFFFFFFFu;

    for (int pass = 0; pass < 10; ++pass) {
        #pragma unroll
        for (int b = 0; b < 32; ++b) histq[b << 8] = 0u;

        #pragma unroll 4
        for (int c = 0; c < MPTS; ++c) {
            float4 t = tile[c];
            float dot = px * t.x + py * t.y + pz * t.z;
            float d2  = fmaxf(fmaf(-2.0f, dot, sq + t.w), 0.0f);
            uint32_t key = __float_as_uint(d2);        // monotone for d2 >= 0
            int bin = (int)(key - lo) >> sh;           // arithmetic shift; clamp under/overflow
            bin = bin < 0 ? 0 : (bin > 31 ? 31 : bin);
            histq[bin << 8] += 1u;
        }

        uint32_t cum = 0, nT = 0;
        int bstar = -1;
        #pragma unroll
        for (int b = 0; b < 32; ++b) {
            cum += histq[b << 8];
            if (bstar < 0 && cum >= KNN) { bstar = b; nT = cum; }
        }

        if (bstar < 31) {
            Tsel = lo + ((uint32_t)(bstar + 1) << sh); // exact: nT keys strictly below Tsel
            if (nT <= CAP) break;
        }
        // refine into boundary bin (uniform for bstar==31: tiles the old bin exactly)
        lo += (uint32_t)bstar << sh;
        sh  = sh > 5 ? sh - 5 : 0;
    }

    // RACE FIX (round 4 bug): hist overlaps bufD, and warps exit the pass loop after
    // different pass counts. Without this barrier, early warps' collect writes into bufD
    // clobber late warps' live histogram bins (word 257s+t aliases word 256s+(t+s)), and
    // late warps' bin-zeroing clobbers collected candidates. All threads reach here.
    __syncthreads();

    // ---- Branch-free collect: all candidates with key < Tsel ----
    uint32_t* bDq = bufD + tid;
    uint16_t* bIq = bufI + tid;
    uint32_t cnt = 0;
    #pragma unroll 4
    for (int c = 0; c < MPTS; ++c) {
        float4 t = tile[c];
        float dot = px * t.x + py * t.y + pz * t.z;
        float d2  = fmaxf(fmaf(-2.0f, dot, sq + t.w), 0.0f);
        uint32_t key = __float_as_uint(d2);
        uint32_t slot = cnt < CAP ? cnt : CAP;         // row CAP = scratch (absorbs non-passing writes)
        bDq[slot * BUFD_STRIDE] = key;                 // unconditional store; a passing candidate
        bIq[slot * BUFI_STRIDE] = (uint16_t)c;         // claims the slot by advancing cnt
        cnt += (key < Tsel) ? 1u : 0u;
    }
    uint32_t n = cnt;
    if (n > CAP) n = CAP;                              // safety rail; slots 0..CAP-1 valid
    if (n < KNN) {                                     // safety rail: pad with +inf keys, valid idx 0
        for (uint32_t i = n; i < KNN; ++i) stk(bDq, bIq, (int)i, ((ull)0xFFFFFFFFu << 16));
        n = KNN;
    }

    // ---- Exact top-33 + ascending sort over <=40 elements (composite key: tie-break by idx) ----
    for (int i = KNN / 2 - 1; i >= 0; --i) {
        ull v = ldk(bDq, bIq, i);
        sift_down(bDq, bIq, i, KNN, v);
    }
    ull root = ldk(bDq, bIq, 0);
    for (uint32_t i = KNN; i < n; ++i) {
        ull v = ldk(bDq, bIq, (int)i);
        if (v < root) { sift_down(bDq, bIq, 0, KNN, v); root = ldk(bDq, bIq, 0); }
    }
    for (int end = KNN - 1; end > 0; --end) {          // heapsort -> ascending (d2, idx) in slots 0..32
        ull maxv = ldk(bDq, bIq, 0);
        ull last = ldk(bDq, bIq, end);
        stk(bDq, bIq, end, maxv);
        sift_down(bDq, bIq, 0, end, last);
    }
    __syncwarp();                                      // output reads same-warp lanes' columns only

    // ---- Coalesced output: warp covers its 32 queries' 32*33 edges linearly ----
    const int warp = tid >> 5;
    const int lane = tid & 31;
    const int q0   = warp << 5;                        // within CTA
    const long E   = (long)BGRAPH * MPTS * KNN;        // 4,325,376
    const long eBase = (long)(base + qoff + q0) * KNN;

    for (int j = lane; j < 32 * KNN; j += 32) {
        int qi = j / KNN;
        int k  = j - qi * KNN;
        int qlocal = q0 + qi;
        int c  = (int)bufI[k * BUFI_STRIDE + qlocal];
        int qq = qoff + qlocal;

        float4 a = tile[c];                            // src = neighbor
        float4 b = tile[qq];                           // dst = center
        float dx = a.x - b.x, dy = a.y - b.y, dz = a.z - b.z;
        float dd = dx * dx + dy * dy + dz * dz;        // reference recomputes from gathered endpoints
        float dist = (dd > 0.0f) ? sqrtf(dd) : 0.0f;

        long e = eBase + j;
        out[e]         = (float)(base + c);
        out[E + e]     = (float)(base + qq);
        out[2 * E + e] = dist;
        out[3 * E + e] = (dist <= RADIUS) ? 1.0f : 0.0f;
    }
}

extern "C" void kernel_launch(void* const* d_in, const int* in_sizes, int n_in,
                              void* d_out, int out_size) {
    const float* pos = (const float*)d_in[0];          // [B*M, 3] float32 (batch input unused: uniform)
    float* out = (float*)d_out;
    cudaFuncSetAttribute(knn_graph_kernel,
                         cudaFuncAttributeMaxDynamicSharedMemorySize, (int)SMEM_BYTES);
    knn_graph_kernel<<<NCTA, QPB, SMEM_BYTES>>>(pos, out);
}